// round 6
// baseline (speedup 1.0000x reference)
#include <cuda_runtime.h>
#include <float.h>

#define Bv 64
#define Nv 1024
#define Dv 128
#define Kv 6
#define CHUNKS 8          // 128 rows per main block, grid = 8 x 64 = 512
#define THR 128

__device__ float  g_ABC[Kv * Dv * 3];           // [k][d][{A,B,C}]
__device__ float  g_partial[Bv * CHUNKS * Dv];  // [b][chunk][d]
__device__ float4 g_sorted[Bv * Nv];            // (xb, yb, x0[orig], y0[orig])
__device__ int    g_sid[Bv * Nv];               // orig index, sorted order
__device__ int    g_count;                      // completion counter (self-resets)

// ---------------------------------------------------------------------------
// Setup: blocks 0..63 -> per-batch bitonic x-sort; 64..111 -> ABC weight fold
// ---------------------------------------------------------------------------
__global__ __launch_bounds__(512) void setup_kernel(
    const float* __restrict__ loc,
    const float* __restrict__ W2d, const float* __restrict__ b2d,
    const float* __restrict__ Wnb)
{
    __shared__ float kx[Nv];
    __shared__ float ky[Nv];
    __shared__ int   kid[Nv];
    const int t = threadIdx.x;

    if (blockIdx.x >= Bv) {
        int wid  = (blockIdx.x - Bv) * 16 + (t >> 5);   // 768 warps = 6k x 128d
        int k    = wid >> 7, d = wid & (Dv - 1);
        int lane = t & 31;
        const float4* w4 = (const float4*)(Wnb + (size_t)d * (Kv * Dv) + k * Dv);
        float4 v  = w4[lane];
        const float4* w2 = (const float4*)W2d;
        float4 p0 = w2[lane * 2], p1 = w2[lane * 2 + 1];
        float4 bb = ((const float4*)b2d)[lane];
        float A = fmaf(v.x, p0.x, fmaf(v.y, p0.z, fmaf(v.z, p1.x, v.w * p1.z)));
        float B = fmaf(v.x, p0.y, fmaf(v.y, p0.w, fmaf(v.z, p1.y, v.w * p1.w)));
        float C = fmaf(v.x, bb.x, fmaf(v.y, bb.y, fmaf(v.z, bb.z, v.w * bb.w)));
#pragma unroll
        for (int s = 16; s > 0; s >>= 1) {
            A += __shfl_xor_sync(0xffffffffu, A, s);
            B += __shfl_xor_sync(0xffffffffu, B, s);
            C += __shfl_xor_sync(0xffffffffu, C, s);
        }
        if (lane == 0) {
            int base = (k * Dv + d) * 3;
            g_ABC[base + 0] = A; g_ABC[base + 1] = B; g_ABC[base + 2] = C;
        }
        return;
    }

    const int b = blockIdx.x;
    const float2* lb = (const float2*)(loc + (size_t)b * Nv * 2);
    for (int i = t; i < Nv; i += 512) {
        float2 p = lb[i];
        kx[i] = p.x; ky[i] = p.y; kid[i] = i;
    }
    __syncthreads();
    for (int k = 2; k <= Nv; k <<= 1) {
        for (int j = k >> 1; j > 0; j >>= 1) {
            for (int i = t; i < Nv; i += 512) {
                int ixj = i ^ j;
                if (ixj > i) {
                    bool up = ((i & k) == 0);
                    float xa = kx[i], xb = kx[ixj];
                    if (up ? (xa > xb) : (xa < xb)) {
                        kx[i] = xb; kx[ixj] = xa;
                        float ya = ky[i]; ky[i] = ky[ixj]; ky[ixj] = ya;
                        int ia = kid[i]; kid[i] = kid[ixj]; kid[ixj] = ia;
                    }
                }
            }
            __syncthreads();
        }
    }
    const float2* l0 = (const float2*)loc;
    for (int i = t; i < Nv; i += 512) {
        int gid = kid[i];
        float2 p0 = l0[gid];
        g_sorted[(size_t)b * Nv + i] = make_float4(kx[i], ky[i], p0.x, p0.y);
        g_sid[(size_t)b * Nv + i]    = gid;
    }
}

// ---------------------------------------------------------------------------
// Main: 128 threads = 128 rows. Warp-uniform union-window scan:
//   lanes own 32 consecutive sorted rows; all lanes process the SAME candidate
//   stream (32 internal, then outward L/R groups of 4). INS is a no-op when
//   dd > d5, so no divergent branches; continuation = one warp-vote per group.
// ---------------------------------------------------------------------------
__global__ __launch_bounds__(THR) void main_kernel(
    const float* __restrict__ deadline,
    const float* __restrict__ W3d, const float* __restrict__ b3d,
    const float* __restrict__ bnb,
    const float* __restrict__ depot, const float* __restrict__ Wdep,
    const float* __restrict__ bdep, float* __restrict__ h_out)
{
    __shared__ float2 sxyv[Nv];        // sorted batch-b coords       8 KB
    __shared__ float2 s0s[Nv];         // batch-0 coords, sorted ord  8 KB
    __shared__ float4 srow[THR];       // (x, y, deadline, origbits)  2 KB
    __shared__ float2 snb[THR * Kv];   // neighbor batch-0 coords     6 KB
    __shared__ float4 sW3[Dv];         // (w0,w1,w2, base)            2 KB
    __shared__ float2 sAB[Kv * Dv];    // (A_k[d], B_k[d])            6 KB
    __shared__ int    sLast;

    const int b = blockIdx.y, chunk = blockIdx.x, t = threadIdx.x;

    {
        const float4* gs = g_sorted + (size_t)b * Nv;
#pragma unroll
        for (int i = 0; i < Nv / THR; i++) {
            float4 q = gs[i * THR + t];
            sxyv[i * THR + t] = make_float2(q.x, q.y);
            s0s[i * THR + t]  = make_float2(q.z, q.w);
        }
    }
    {
        float sumC = 0.f;
#pragma unroll
        for (int k = 0; k < Kv; k++) {
            int base = (k * Dv + t) * 3;
            sAB[k * Dv + t] = make_float2(g_ABC[base], g_ABC[base + 1]);
            sumC += g_ABC[base + 2];
        }
        sW3[t] = make_float4(W3d[t * 3 + 0], W3d[t * 3 + 1], W3d[t * 3 + 2],
                             b3d[t] + bnb[t] + sumC);
    }
    __syncthreads();

    // ---- phase 2: warp-uniform scan ----
    const int w    = t >> 5;                  // warp 0..3
    const int base = chunk * THR + w * 32;    // warp's first sorted row
    const int p    = base + (t & 31);         // this lane's row
    const float2 m = sxyv[p];
    const float mx = m.x, my = m.y;

    float d0 = FLT_MAX, d1 = FLT_MAX, d2 = FLT_MAX,
          d3 = FLT_MAX, d4 = FLT_MAX, d5 = FLT_MAX;
    int   i0 = 0, i1 = 0, i2 = 0, i3 = 0, i4 = 0, i5 = 0;

#define INS(dd, cj)  do {                                                    \
        bool c0 = dd < d0, c1 = dd < d1, c2 = dd < d2,                       \
             c3 = dd < d3, c4 = dd < d4, c5 = dd < d5;                       \
        float m0 = fmaxf(d0, dd), m1 = fmaxf(d1, dd), m2 = fmaxf(d2, dd),    \
              m3 = fmaxf(d3, dd), m4 = fmaxf(d4, dd);                        \
        int   w0 = c0 ? i0 : cj, w1 = c1 ? i1 : cj, w2 = c2 ? i2 : cj,       \
              w3 = c3 ? i3 : cj, w4 = c4 ? i4 : cj;                          \
        d5 = c5 ? m4 : d5;  i5 = c5 ? w4 : i5;                               \
        d4 = c4 ? m3 : d4;  i4 = c4 ? w3 : i4;                               \
        d3 = c3 ? m2 : d3;  i3 = c3 ? w2 : i3;                               \
        d2 = c2 ? m1 : d2;  i2 = c2 ? w1 : i2;                               \
        d1 = c1 ? m0 : d1;  i1 = c1 ? w0 : i1;                               \
        d0 = c0 ? dd : d0;  i0 = c0 ? cj : i0;                               \
    } while (0)

#define CAND(cj, DXX) {                                                     \
        float2 cv = sxyv[cj];                                               \
        float dx  = __fadd_rn(cv.x, -mx);                                   \
        float dy  = __fadd_rn(cv.y, -my);                                   \
        DXX = __fmul_rn(dx, dx);                                            \
        float dd  = __fadd_rn(DXX, __fmul_rn(dy, dy));                      \
        INS(dd, cj);                                                        \
    }

    {   // internal 32 candidates (includes self: dd = 0 self-inserts)
        float dxx;
#pragma unroll 4
        for (int q = 0; q < 32; q++) CAND(base + q, dxx);
    }
    {   // leftward, groups of 4, warp-vote prune on farthest candidate
        int j = base - 1; bool go = (j >= 0);
        while (go && j >= 3) {
            float x0x, x1x, x2x, x3x;
            CAND(j, x0x); CAND(j-1, x1x); CAND(j-2, x2x); CAND(j-3, x3x);
            go = __any_sync(0xffffffffu, x3x <= d5);  // dxx monotone; dd >= dxx
            j -= 4;
        }
        while (go && j >= 0) {
            float xx; CAND(j, xx);
            go = __any_sync(0xffffffffu, xx <= d5);
            j--;
        }
    }
    {   // rightward
        int j = base + 32; bool go = (j < Nv);
        while (go && j <= Nv - 4) {
            float x0x, x1x, x2x, x3x;
            CAND(j, x0x); CAND(j+1, x1x); CAND(j+2, x2x); CAND(j+3, x3x);
            go = __any_sync(0xffffffffu, x3x <= d5);
            j += 4;
        }
        while (go && j < Nv) {
            float xx; CAND(j, xx);
            go = __any_sync(0xffffffffu, xx <= d5);
            j++;
        }
    }
#undef CAND
#undef INS

    const int rloc = t;                    // one row per thread
    snb[rloc*Kv+0] = s0s[i0]; snb[rloc*Kv+1] = s0s[i1]; snb[rloc*Kv+2] = s0s[i2];
    snb[rloc*Kv+3] = s0s[i3]; snb[rloc*Kv+4] = s0s[i4]; snb[rloc*Kv+5] = s0s[i5];
    {
        int orig = g_sid[(size_t)b * Nv + p];
        srow[rloc] = make_float4(mx, my, deadline[(size_t)b * Nv + orig],
                                 __int_as_float(orig));
    }
    __syncthreads();

    // ---- phase 3: features; thread t = dim d, loop over 128 rows ----
    const int d    = t;
    const float4 wv = sW3[d];
    float A[Kv], Bc[Kv];
#pragma unroll
    for (int k = 0; k < Kv; k++) { float2 ab = sAB[k * Dv + d]; A[k] = ab.x; Bc[k] = ab.y; }

    float acc = 0.f;
#pragma unroll 2
    for (int r = 0; r < THR; r++) {
        float4 rd = srow[r];               // broadcast LDS.128
        float v = wv.w;
        v = fmaf(rd.x, wv.x, v);
        v = fmaf(rd.y, wv.y, v);
        v = fmaf(rd.z, wv.z, v);
#pragma unroll
        for (int k = 0; k < Kv; k++) {
            float2 nb = snb[r * Kv + k];   // broadcast LDS.64
            v = fmaf(nb.x, A[k], v);
            v = fmaf(nb.y, Bc[k], v);
        }
        v = fmaxf(v, 0.01f * v);           // leaky_relu(0.01)
        int orow = __float_as_int(rd.w);
        h_out[((size_t)b * 1025 + 1 + orow) * Dv + d] = v;
        acc += v;
    }
    g_partial[((size_t)b * CHUNKS + chunk) * Dv + d] = acc;

    // ---- fused tail: last finishing block computes depot row + means ----
    __threadfence();
    if (t == 0) sLast = (atomicAdd(&g_count, 1) == CHUNKS * Bv - 1) ? 1 : 0;
    __syncthreads();
    if (sLast) {
        float w0 = Wdep[t * 2 + 0], w1 = Wdep[t * 2 + 1], bd = bdep[t];
        for (int bb = 0; bb < Bv; bb++) {
            float v = bd;
            v = fmaf(depot[bb * 2 + 0], w0, v);
            v = fmaf(depot[bb * 2 + 1], w1, v);
            v = fmaxf(v, 0.01f * v);
            h_out[(size_t)bb * 1025 * Dv + t] = v;       // h[bb, 0, d]
            float s = v;
#pragma unroll
            for (int c = 0; c < CHUNKS; c++)
                s += g_partial[((size_t)bb * CHUNKS + c) * Dv + t];
            h_out[(size_t)Bv * 1025 * Dv + bb * Dv + t] = s / 1025.0f;
        }
        if (t == 0) g_count = 0;           // reset for next graph replay
    }
}

// ---------------------------------------------------------------------------
extern "C" void kernel_launch(void* const* d_in, const int* in_sizes, int n_in,
                              void* d_out, int out_size)
{
    const float* loc      = (const float*)d_in[0];
    const float* deadline = (const float*)d_in[1];
    const float* depot    = (const float*)d_in[2];
    const float* W3d      = (const float*)d_in[3];
    const float* b3d      = (const float*)d_in[4];
    const float* W2d      = (const float*)d_in[5];
    const float* b2d      = (const float*)d_in[6];
    const float* Wnb      = (const float*)d_in[7];
    const float* bnb      = (const float*)d_in[8];
    const float* Wdep     = (const float*)d_in[9];
    const float* bdep     = (const float*)d_in[10];
    float* out = (float*)d_out;

    setup_kernel<<<Bv + 48, 512>>>(loc, W2d, b2d, Wnb);
    dim3 grid(CHUNKS, Bv);
    main_kernel<<<grid, THR>>>(deadline, W3d, b3d, bnb,
                               depot, Wdep, bdep, out);
}

// round 7
// speedup vs baseline: 1.1536x; 1.1536x over previous
#include <cuda_runtime.h>
#include <float.h>

#define Bv 64
#define Nv 1024
#define Dv 128
#define Kv 6
#define CHUNKS 16         // 64 rows per main block, grid = 16 x 64 = 1024
#define RPB 64            // rows per block
#define THR 128
#define MARGIN 0.001f     // > 1/1024 bucket width (counting-sort disorder bound)

__device__ float  g_ABC[Kv * Dv * 3];           // [k][d][{A,B,C}]
__device__ float  g_partial[Bv * CHUNKS * Dv];  // [b][chunk][d]
__device__ float4 g_sorted[Bv * Nv];            // (xb, yb, x0[orig], y0[orig])
__device__ int    g_sid[Bv * Nv];               // orig index, bucket-sorted order
__device__ int    g_count;                      // completion counter (self-resets)

// ---------------------------------------------------------------------------
// Setup: blocks 0..63  -> per-batch counting sort by x-bucket (1024 buckets)
//        blocks 64..111 -> ABC weight fold (one warp per (k,d))
// ---------------------------------------------------------------------------
__global__ __launch_bounds__(512) void setup_kernel(
    const float* __restrict__ loc,
    const float* __restrict__ W2d, const float* __restrict__ b2d,
    const float* __restrict__ Wnb)
{
    __shared__ int cnt[Nv];
    __shared__ int wsum[16];
    const int t = threadIdx.x;

    if (blockIdx.x >= Bv) {
        int wid  = (blockIdx.x - Bv) * 16 + (t >> 5);   // 768 warps = 6k x 128d
        int k    = wid >> 7, d = wid & (Dv - 1);
        int lane = t & 31;
        const float4* w4 = (const float4*)(Wnb + (size_t)d * (Kv * Dv) + k * Dv);
        float4 v  = w4[lane];
        const float4* w2 = (const float4*)W2d;
        float4 p0 = w2[lane * 2], p1 = w2[lane * 2 + 1];
        float4 bb = ((const float4*)b2d)[lane];
        float A = fmaf(v.x, p0.x, fmaf(v.y, p0.z, fmaf(v.z, p1.x, v.w * p1.z)));
        float B = fmaf(v.x, p0.y, fmaf(v.y, p0.w, fmaf(v.z, p1.y, v.w * p1.w)));
        float C = fmaf(v.x, bb.x, fmaf(v.y, bb.y, fmaf(v.z, bb.z, v.w * bb.w)));
#pragma unroll
        for (int s = 16; s > 0; s >>= 1) {
            A += __shfl_xor_sync(0xffffffffu, A, s);
            B += __shfl_xor_sync(0xffffffffu, B, s);
            C += __shfl_xor_sync(0xffffffffu, C, s);
        }
        if (lane == 0) {
            int base = (k * Dv + d) * 3;
            g_ABC[base + 0] = A; g_ABC[base + 1] = B; g_ABC[base + 2] = C;
        }
        return;
    }

    // ---- counting sort by x-bucket ----
    const int b = blockIdx.x;
    const float2* lb = (const float2*)(loc + (size_t)b * Nv * 2);
    const float2* l0 = (const float2*)loc;

    cnt[t] = 0; cnt[t + 512] = 0;
    float2 pa = lb[t], pb = lb[t + 512];
    float2 qa = l0[t], qb = l0[t + 512];
    __syncthreads();
    int bka = min((int)(pa.x * 1024.0f), Nv - 1);
    int bkb = min((int)(pb.x * 1024.0f), Nv - 1);
    atomicAdd(&cnt[bka], 1);
    atomicAdd(&cnt[bkb], 1);
    __syncthreads();

    // exclusive scan over 1024 counters (2 per thread)
    int c0 = cnt[2 * t], c1 = cnt[2 * t + 1];
    int s  = c0 + c1;
    int lane = t & 31;
    int v = s;
#pragma unroll
    for (int o = 1; o < 32; o <<= 1) {
        int u = __shfl_up_sync(0xffffffffu, v, o);
        if (lane >= o) v += u;
    }
    if (lane == 31) wsum[t >> 5] = v;
    __syncthreads();
    if (t < 16) {
        int wv = wsum[t], vv = wv;
#pragma unroll
        for (int o = 1; o < 16; o <<= 1) {
            int u = __shfl_up_sync(0x0000ffffu, vv, o);
            if (t >= o) vv += u;
        }
        wsum[t] = vv - wv;                       // exclusive warp offsets
    }
    __syncthreads();
    int excl = wsum[t >> 5] + (v - s);           // exclusive for this pair
    cnt[2 * t]     = excl;                       // bucket start offsets
    cnt[2 * t + 1] = excl + c0;
    __syncthreads();

    // scatter (within-bucket order arbitrary; selection is order-independent)
    int posA = atomicAdd(&cnt[bka], 1);
    g_sorted[(size_t)b * Nv + posA] = make_float4(pa.x, pa.y, qa.x, qa.y);
    g_sid[(size_t)b * Nv + posA]    = t;
    int posB = atomicAdd(&cnt[bkb], 1);
    g_sorted[(size_t)b * Nv + posB] = make_float4(pb.x, pb.y, qb.x, qb.y);
    g_sid[(size_t)b * Nv + posB]    = t + 512;
}

// ---------------------------------------------------------------------------
// Main: 128 threads = 4 warps. Warp pair per 32-row group:
//   both warps scan the 32-candidate core with disjoint insert masks
//   (dir0: j<=p incl. self; dir1: j>p), then dir0 scans left, dir1 right,
//   warp-vote pruned with a 1-bucket safety margin. Two-pointer merge.
// ---------------------------------------------------------------------------
__global__ __launch_bounds__(THR) void main_kernel(
    const float* __restrict__ deadline,
    const float* __restrict__ W3d, const float* __restrict__ b3d,
    const float* __restrict__ bnb,
    const float* __restrict__ depot, const float* __restrict__ Wdep,
    const float* __restrict__ bdep, float* __restrict__ h_out)
{
    __shared__ float2 sxyv[Nv];        // sorted batch-b coords       8 KB
    __shared__ float2 s0s[Nv];         // batch-0 coords, sorted ord  8 KB
    __shared__ float4 srow[RPB];       // (x, y, deadline, origbits)  1 KB
    __shared__ float2 snb[RPB * Kv];   // neighbor batch-0 coords     3 KB
    __shared__ float4 sW3[Dv];         // (w0,w1,w2, base)            2 KB
    __shared__ float2 sAB[Kv * Dv];    // (A_k[d], B_k[d])            6 KB
    __shared__ float  pdm[RPB * Kv];   // dir1 top-6 dists          1.5 KB
    __shared__ int    pim[RPB * Kv];   // dir1 top-6 sorted pos     1.5 KB
    __shared__ int    sLast;

    const int b = blockIdx.y, chunk = blockIdx.x, t = threadIdx.x;

    {
        const float4* gs = g_sorted + (size_t)b * Nv;
#pragma unroll
        for (int i = 0; i < Nv / THR; i++) {
            float4 q = gs[i * THR + t];
            sxyv[i * THR + t] = make_float2(q.x, q.y);
            s0s[i * THR + t]  = make_float2(q.z, q.w);
        }
    }
    {
        float sumC = 0.f;
#pragma unroll
        for (int k = 0; k < Kv; k++) {
            int base = (k * Dv + t) * 3;
            sAB[k * Dv + t] = make_float2(g_ABC[base], g_ABC[base + 1]);
            sumC += g_ABC[base + 2];
        }
        sW3[t] = make_float4(W3d[t * 3 + 0], W3d[t * 3 + 1], W3d[t * 3 + 2],
                             b3d[t] + bnb[t] + sumC);
    }
    __syncthreads();

    // ---- phase 2 ----
    const int w    = t >> 5, lane = t & 31;
    const int g    = w >> 1, dir = w & 1;       // group 0/1, direction 0/1
    const int base = chunk * RPB + g * 32;
    const int p    = base + lane;
    const int rloc = g * 32 + lane;
    const float2 m = sxyv[p];
    const float mx = m.x, my = m.y;

    float d0 = FLT_MAX, d1 = FLT_MAX, d2 = FLT_MAX,
          d3 = FLT_MAX, d4 = FLT_MAX, d5 = FLT_MAX;
    int   i0 = 0, i1 = 0, i2 = 0, i3 = 0, i4 = 0, i5 = 0;

#define INS(dd, cj)  do {                                                    \
        bool c0 = dd < d0, c1 = dd < d1, c2 = dd < d2,                       \
             c3 = dd < d3, c4 = dd < d4, c5 = dd < d5;                       \
        float m0 = fmaxf(d0, dd), m1 = fmaxf(d1, dd), m2 = fmaxf(d2, dd),    \
              m3 = fmaxf(d3, dd), m4 = fmaxf(d4, dd);                        \
        int   w0 = c0 ? i0 : cj, w1 = c1 ? i1 : cj, w2 = c2 ? i2 : cj,       \
              w3 = c3 ? i3 : cj, w4 = c4 ? i4 : cj;                          \
        d5 = c5 ? m4 : d5;  i5 = c5 ? w4 : i5;                               \
        d4 = c4 ? m3 : d4;  i4 = c4 ? w3 : i4;                               \
        d3 = c3 ? m2 : d3;  i3 = c3 ? w2 : i3;                               \
        d2 = c2 ? m1 : d2;  i2 = c2 ? w1 : i2;                               \
        d1 = c1 ? m0 : d1;  i1 = c1 ? w0 : i1;                               \
        d0 = c0 ? dd : d0;  i0 = c0 ? cj : i0;                               \
    } while (0)

#define CAND(cj, DX) {                                                      \
        float2 cv = sxyv[cj];                                               \
        float dx  = __fadd_rn(cv.x, -mx);                                   \
        float dy  = __fadd_rn(cv.y, -my);                                   \
        DX = dx;                                                            \
        float dd  = __fadd_rn(__fmul_rn(dx, dx), __fmul_rn(dy, dy));        \
        INS(dd, cj);                                                        \
    }

    {   // core: 32 candidates, disjoint insert masks (self lands in dir0)
        float dxx;
#pragma unroll 4
        for (int q = 0; q < 32; q++) {
            int j = base + q;
            float2 cv = sxyv[j];
            float dx  = __fadd_rn(cv.x, -mx);
            float dy  = __fadd_rn(cv.y, -my);
            float dd  = __fadd_rn(__fmul_rn(dx, dx), __fmul_rn(dy, dy));
            bool keep = dir ? (j > p) : (j <= p);
            float ddm = keep ? dd : FLT_MAX;
            INS(ddm, j);
            (void)dxx;
        }
    }
    if (dir == 0) {                        // leftward outward
        int j = base - 1; bool go = (j >= 0);
        while (go && j >= 3) {
            float x0d, x1d, x2d, x3d;
            CAND(j, x0d); CAND(j-1, x1d); CAND(j-2, x2d); CAND(j-3, x3d);
            float ax = fmaxf(fabsf(x3d) - MARGIN, 0.f);
            go = __any_sync(0xffffffffu, __fmul_rn(ax, ax) <= d5);
            j -= 4;
        }
        while (go && j >= 0) {
            float xd; CAND(j, xd);
            float ax = fmaxf(fabsf(xd) - MARGIN, 0.f);
            go = __any_sync(0xffffffffu, __fmul_rn(ax, ax) <= d5);
            j--;
        }
    } else {                               // rightward outward
        int j = base + 32; bool go = (j < Nv);
        while (go && j <= Nv - 4) {
            float x0d, x1d, x2d, x3d;
            CAND(j, x0d); CAND(j+1, x1d); CAND(j+2, x2d); CAND(j+3, x3d);
            float ax = fmaxf(fabsf(x3d) - MARGIN, 0.f);
            go = __any_sync(0xffffffffu, __fmul_rn(ax, ax) <= d5);
            j += 4;
        }
        while (go && j < Nv) {
            float xd; CAND(j, xd);
            float ax = fmaxf(fabsf(xd) - MARGIN, 0.f);
            go = __any_sync(0xffffffffu, __fmul_rn(ax, ax) <= d5);
            j++;
        }
        pdm[rloc*Kv+0]=d0; pdm[rloc*Kv+1]=d1; pdm[rloc*Kv+2]=d2;
        pdm[rloc*Kv+3]=d3; pdm[rloc*Kv+4]=d4; pdm[rloc*Kv+5]=d5;
        pim[rloc*Kv+0]=i0; pim[rloc*Kv+1]=i1; pim[rloc*Kv+2]=i2;
        pim[rloc*Kv+3]=i3; pim[rloc*Kv+4]=i4; pim[rloc*Kv+5]=i5;
    }
#undef CAND
#undef INS
    __syncthreads();

    if (dir == 0) {                        // merge disjoint lists, 6 steps
        float b0=pdm[rloc*Kv+0], b1=pdm[rloc*Kv+1], b2=pdm[rloc*Kv+2],
              b3=pdm[rloc*Kv+3], b4=pdm[rloc*Kv+4], b5=pdm[rloc*Kv+5];
        int   y0=pim[rloc*Kv+0], y1=pim[rloc*Kv+1], y2=pim[rloc*Kv+2],
              y3=pim[rloc*Kv+3], y4=pim[rloc*Kv+4], y5=pim[rloc*Kv+5];
#pragma unroll
        for (int s = 0; s < Kv; s++) {
            bool ta = (d0 <= b0);
            int sel = ta ? i0 : y0;
            snb[rloc * Kv + s] = s0s[sel];
            if (ta) { d0=d1; d1=d2; d2=d3; d3=d4; d4=d5; d5=FLT_MAX;
                      i0=i1; i1=i2; i2=i3; i3=i4; i4=i5; }
            else    { b0=b1; b1=b2; b2=b3; b3=b4; b4=b5; b5=FLT_MAX;
                      y0=y1; y1=y2; y2=y3; y3=y4; y4=y5; }
        }
        int orig = g_sid[(size_t)b * Nv + p];
        srow[rloc] = make_float4(mx, my, deadline[(size_t)b * Nv + orig],
                                 __int_as_float(orig));
    }
    __syncthreads();

    // ---- phase 3: thread t = dim d, loop over 64 rows ----
    const int d = t;
    const float4 wv = sW3[d];
    float A[Kv], Bc[Kv];
#pragma unroll
    for (int k = 0; k < Kv; k++) { float2 ab = sAB[k * Dv + d]; A[k] = ab.x; Bc[k] = ab.y; }

    float acc = 0.f;
#pragma unroll 2
    for (int r = 0; r < RPB; r++) {
        float4 rd = srow[r];               // broadcast LDS.128
        float v = wv.w;
        v = fmaf(rd.x, wv.x, v);
        v = fmaf(rd.y, wv.y, v);
        v = fmaf(rd.z, wv.z, v);
#pragma unroll
        for (int k = 0; k < Kv; k++) {
            float2 nb = snb[r * Kv + k];   // broadcast LDS.64
            v = fmaf(nb.x, A[k], v);
            v = fmaf(nb.y, Bc[k], v);
        }
        v = fmaxf(v, 0.01f * v);           // leaky_relu(0.01)
        int orow = __float_as_int(rd.w);
        h_out[((size_t)b * 1025 + 1 + orow) * Dv + d] = v;
        acc += v;
    }
    g_partial[((size_t)b * CHUNKS + chunk) * Dv + d] = acc;

    // ---- fused tail: last finishing block computes depot row + means ----
    __threadfence();
    if (t == 0) sLast = (atomicAdd(&g_count, 1) == CHUNKS * Bv - 1) ? 1 : 0;
    __syncthreads();
    if (sLast) {
        float w0 = Wdep[t * 2 + 0], w1 = Wdep[t * 2 + 1], bd = bdep[t];
        for (int bb = 0; bb < Bv; bb++) {
            float v = bd;
            v = fmaf(depot[bb * 2 + 0], w0, v);
            v = fmaf(depot[bb * 2 + 1], w1, v);
            v = fmaxf(v, 0.01f * v);
            h_out[(size_t)bb * 1025 * Dv + t] = v;       // h[bb, 0, d]
            float s = v;
#pragma unroll
            for (int c = 0; c < CHUNKS; c++)
                s += g_partial[((size_t)bb * CHUNKS + c) * Dv + t];
            h_out[(size_t)Bv * 1025 * Dv + bb * Dv + t] = s / 1025.0f;
        }
        if (t == 0) g_count = 0;           // reset for next graph replay
    }
}

// ---------------------------------------------------------------------------
extern "C" void kernel_launch(void* const* d_in, const int* in_sizes, int n_in,
                              void* d_out, int out_size)
{
    const float* loc      = (const float*)d_in[0];
    const float* deadline = (const float*)d_in[1];
    const float* depot    = (const float*)d_in[2];
    const float* W3d      = (const float*)d_in[3];
    const float* b3d      = (const float*)d_in[4];
    const float* W2d      = (const float*)d_in[5];
    const float* b2d      = (const float*)d_in[6];
    const float* Wnb      = (const float*)d_in[7];
    const float* bnb      = (const float*)d_in[8];
    const float* Wdep     = (const float*)d_in[9];
    const float* bdep     = (const float*)d_in[10];
    float* out = (float*)d_out;

    setup_kernel<<<Bv + 48, 512>>>(loc, W2d, b2d, Wnb);
    dim3 grid(CHUNKS, Bv);
    main_kernel<<<grid, THR>>>(deadline, W3d, b3d, bnb,
                               depot, Wdep, bdep, out);
}

// round 8
// speedup vs baseline: 1.3290x; 1.1520x over previous
#include <cuda_runtime.h>
#include <float.h>

#define Bv 64
#define Nv 1024
#define Dv 128
#define Kv 6
#define CHUNKS 8          // 128 rows per main block, grid = 8 x 64 = 512
#define RPB 128
#define THR 128
#define MARGIN 0.001f     // > 1/1024 bucket width (counting-sort disorder bound)

typedef unsigned long long ull;

__device__ float  g_ABC[Kv * Dv * 3];           // [k][d][{A,B,C}]
__device__ float  g_partial[Bv * CHUNKS * Dv];  // [b][chunk][d]
__device__ float4 g_pts[Bv * Nv];               // (xb, yb, deadline, orig) sorted
__device__ float2 g_p0[Bv * Nv];                // (x0, y0) sorted order
__device__ int    g_count;                      // completion counter (self-resets)

// ---- packed f32x2 helpers (per-half rn == scalar rounding) ----
__device__ __forceinline__ ull f2add(ull a, ull b) {
    ull r; asm("add.rn.f32x2 %0,%1,%2;" : "=l"(r) : "l"(a), "l"(b)); return r;
}
__device__ __forceinline__ ull f2mul(ull a, ull b) {
    ull r; asm("mul.rn.f32x2 %0,%1,%2;" : "=l"(r) : "l"(a), "l"(b)); return r;
}
__device__ __forceinline__ ull f2fma(ull a, ull b, ull c) {
    ull r; asm("fma.rn.f32x2 %0,%1,%2,%3;" : "=l"(r) : "l"(a), "l"(b), "l"(c)); return r;
}
__device__ __forceinline__ ull f2pack(float lo, float hi) {
    ull r; asm("mov.b64 %0,{%1,%2};" : "=l"(r) : "f"(lo), "f"(hi)); return r;
}
__device__ __forceinline__ void f2unpack(ull v, float& lo, float& hi) {
    asm("mov.b64 {%0,%1},%2;" : "=f"(lo), "=f"(hi) : "l"(v));
}

// ---------------------------------------------------------------------------
// Setup: blocks 0..63  -> per-batch counting sort by x-bucket (1024 buckets)
//        blocks 64..111 -> ABC weight fold (one warp per (k,d))
// ---------------------------------------------------------------------------
__global__ __launch_bounds__(512) void setup_kernel(
    const float* __restrict__ loc, const float* __restrict__ deadline,
    const float* __restrict__ W2d, const float* __restrict__ b2d,
    const float* __restrict__ Wnb)
{
    __shared__ int cnt[Nv];
    __shared__ int wsum[16];
    const int t = threadIdx.x;

    if (blockIdx.x >= Bv) {
        int wid  = (blockIdx.x - Bv) * 16 + (t >> 5);   // 768 warps = 6k x 128d
        int k    = wid >> 7, d = wid & (Dv - 1);
        int lane = t & 31;
        const float4* w4 = (const float4*)(Wnb + (size_t)d * (Kv * Dv) + k * Dv);
        float4 v  = w4[lane];
        const float4* w2 = (const float4*)W2d;
        float4 p0 = w2[lane * 2], p1 = w2[lane * 2 + 1];
        float4 bb = ((const float4*)b2d)[lane];
        float A = fmaf(v.x, p0.x, fmaf(v.y, p0.z, fmaf(v.z, p1.x, v.w * p1.z)));
        float B = fmaf(v.x, p0.y, fmaf(v.y, p0.w, fmaf(v.z, p1.y, v.w * p1.w)));
        float C = fmaf(v.x, bb.x, fmaf(v.y, bb.y, fmaf(v.z, bb.z, v.w * bb.w)));
#pragma unroll
        for (int s = 16; s > 0; s >>= 1) {
            A += __shfl_xor_sync(0xffffffffu, A, s);
            B += __shfl_xor_sync(0xffffffffu, B, s);
            C += __shfl_xor_sync(0xffffffffu, C, s);
        }
        if (lane == 0) {
            int base = (k * Dv + d) * 3;
            g_ABC[base + 0] = A; g_ABC[base + 1] = B; g_ABC[base + 2] = C;
        }
        return;
    }

    // ---- counting sort by x-bucket ----
    const int b = blockIdx.x;
    const float2* lb = (const float2*)(loc + (size_t)b * Nv * 2);
    const float2* l0 = (const float2*)loc;

    cnt[t] = 0; cnt[t + 512] = 0;
    float2 pa = lb[t], pb = lb[t + 512];
    float2 qa = l0[t], qb = l0[t + 512];
    float dla = deadline[(size_t)b * Nv + t];
    float dlb = deadline[(size_t)b * Nv + t + 512];
    __syncthreads();
    int bka = min((int)(pa.x * 1024.0f), Nv - 1);
    int bkb = min((int)(pb.x * 1024.0f), Nv - 1);
    atomicAdd(&cnt[bka], 1);
    atomicAdd(&cnt[bkb], 1);
    __syncthreads();

    // exclusive scan over 1024 counters (2 per thread)
    int c0 = cnt[2 * t], c1 = cnt[2 * t + 1];
    int s  = c0 + c1;
    int lane = t & 31;
    int v = s;
#pragma unroll
    for (int o = 1; o < 32; o <<= 1) {
        int u = __shfl_up_sync(0xffffffffu, v, o);
        if (lane >= o) v += u;
    }
    if (lane == 31) wsum[t >> 5] = v;
    __syncthreads();
    if (t < 16) {
        int wv = wsum[t], vv = wv;
#pragma unroll
        for (int o = 1; o < 16; o <<= 1) {
            int u = __shfl_up_sync(0x0000ffffu, vv, o);
            if (t >= o) vv += u;
        }
        wsum[t] = vv - wv;
    }
    __syncthreads();
    int excl = wsum[t >> 5] + (v - s);
    cnt[2 * t]     = excl;
    cnt[2 * t + 1] = excl + c0;
    __syncthreads();

    int posA = atomicAdd(&cnt[bka], 1);
    g_pts[(size_t)b * Nv + posA] = make_float4(pa.x, pa.y, dla, __int_as_float(t));
    g_p0[(size_t)b * Nv + posA]  = qa;
    int posB = atomicAdd(&cnt[bkb], 1);
    g_pts[(size_t)b * Nv + posB] = make_float4(pb.x, pb.y, dlb, __int_as_float(t + 512));
    g_p0[(size_t)b * Nv + posB]  = qb;
}

// ---------------------------------------------------------------------------
// Main: 128 threads = 4 warps; warp w owns rows [w*32, w*32+32) (two-sided
// warp-uniform union-window scan, branchless INS, warp-vote prune w/ margin).
// ---------------------------------------------------------------------------
__global__ __launch_bounds__(THR) void main_kernel(
    const float* __restrict__ W3d, const float* __restrict__ b3d,
    const float* __restrict__ bnb,
    const float* __restrict__ depot, const float* __restrict__ Wdep,
    const float* __restrict__ bdep, float* __restrict__ h_out)
{
    __shared__ __align__(16) float2 sxyv[Nv];      // sorted batch-b coords  8 KB
    __shared__ __align__(16) float2 s0s[Nv];       // batch-0 coords, sorted 8 KB
    __shared__ float4 srow[RPB];                   // (x,y,deadline,orig)    2 KB
    __shared__ __align__(16) float2 snb[RPB * Kv]; // neighbor b0 coords     6 KB
    __shared__ float4 sW3[Dv];                     // (w0,w1,w2, base)       2 KB
    __shared__ __align__(16) float2 sAB[Kv * Dv];  // (A_k[d], B_k[d])       6 KB
    __shared__ int    sLast;

    const int b = blockIdx.y, chunk = blockIdx.x, t = threadIdx.x;

    {
        const float4* gp = g_pts + (size_t)b * Nv;
        const float2* g0 = g_p0  + (size_t)b * Nv;
#pragma unroll
        for (int i = 0; i < Nv / THR; i++) {
            float4 q = gp[i * THR + t];
            sxyv[i * THR + t] = make_float2(q.x, q.y);
            s0s[i * THR + t]  = g0[i * THR + t];
        }
        srow[t] = gp[chunk * RPB + t];             // own rows: full record
    }
    {
        float sumC = 0.f;
#pragma unroll
        for (int k = 0; k < Kv; k++) {
            int base = (k * Dv + t) * 3;
            sAB[k * Dv + t] = make_float2(g_ABC[base], g_ABC[base + 1]);
            sumC += g_ABC[base + 2];
        }
        sW3[t] = make_float4(W3d[t * 3 + 0], W3d[t * 3 + 1], W3d[t * 3 + 2],
                             b3d[t] + bnb[t] + sumC);
    }
    __syncthreads();

    // ---- phase 2: warp-uniform two-sided scan ----
    const int w    = t >> 5;
    const int base = chunk * RPB + w * 32;
    const int p    = base + (t & 31);
    const float2 m = sxyv[p];
    const ull negm = f2pack(-m.x, -m.y);

    float d0 = FLT_MAX, d1 = FLT_MAX, d2 = FLT_MAX,
          d3 = FLT_MAX, d4 = FLT_MAX, d5 = FLT_MAX;
    int   i0 = 0, i1 = 0, i2 = 0, i3 = 0, i4 = 0, i5 = 0;

#define INS(dd, cj)  do {                                                    \
        bool c0 = dd < d0, c1 = dd < d1, c2 = dd < d2,                       \
             c3 = dd < d3, c4 = dd < d4, c5 = dd < d5;                       \
        float m0 = fmaxf(d0, dd), m1 = fmaxf(d1, dd), m2 = fmaxf(d2, dd),    \
              m3 = fmaxf(d3, dd), m4 = fmaxf(d4, dd);                        \
        int   w0 = c0 ? i0 : cj, w1 = c1 ? i1 : cj, w2 = c2 ? i2 : cj,       \
              w3 = c3 ? i3 : cj, w4 = c4 ? i4 : cj;                          \
        d5 = c5 ? m4 : d5;  i5 = c5 ? w4 : i5;                               \
        d4 = c4 ? m3 : d4;  i4 = c4 ? w3 : i4;                               \
        d3 = c3 ? m2 : d3;  i3 = c3 ? w2 : i3;                               \
        d2 = c2 ? m1 : d2;  i2 = c2 ? w1 : i2;                               \
        d1 = c1 ? m0 : d1;  i1 = c1 ? w0 : i1;                               \
        d0 = c0 ? dd : d0;  i0 = c0 ? cj : i0;                               \
    } while (0)

    // packed CAND: diff = cv + (-m); sq = diff*diff; dd = lo+hi (exact rn)
#define CAND(cj, DX) {                                                      \
        ull cvu  = *(const ull*)&sxyv[cj];                                  \
        ull diff = f2add(cvu, negm);                                        \
        ull sq   = f2mul(diff, diff);                                       \
        float qlo, qhi, dlo, dhi;                                           \
        f2unpack(sq, qlo, qhi);                                             \
        f2unpack(diff, dlo, dhi); (void)dhi;                                \
        DX = dlo;                                                           \
        float dd = __fadd_rn(qlo, qhi);                                     \
        INS(dd, cj);                                                        \
    }

    {   // core 32 candidates (self dd=0 self-inserts)
        float dxx;
#pragma unroll 8
        for (int q = 0; q < 32; q++) CAND(base + q, dxx);
    }
    {   // leftward, groups of 4, warp-vote prune with bucket margin
        int j = base - 1; bool go = (j >= 0);
        while (go && j >= 3) {
            float x0d, x1d, x2d, x3d;
            CAND(j, x0d); CAND(j-1, x1d); CAND(j-2, x2d); CAND(j-3, x3d);
            float ax = fmaxf(fabsf(x3d) - MARGIN, 0.f);
            go = __any_sync(0xffffffffu, __fmul_rn(ax, ax) <= d5);
            j -= 4;
        }
        while (go && j >= 0) {
            float xd; CAND(j, xd);
            float ax = fmaxf(fabsf(xd) - MARGIN, 0.f);
            go = __any_sync(0xffffffffu, __fmul_rn(ax, ax) <= d5);
            j--;
        }
    }
    {   // rightward
        int j = base + 32; bool go = (j < Nv);
        while (go && j <= Nv - 4) {
            float x0d, x1d, x2d, x3d;
            CAND(j, x0d); CAND(j+1, x1d); CAND(j+2, x2d); CAND(j+3, x3d);
            float ax = fmaxf(fabsf(x3d) - MARGIN, 0.f);
            go = __any_sync(0xffffffffu, __fmul_rn(ax, ax) <= d5);
            j += 4;
        }
        while (go && j < Nv) {
            float xd; CAND(j, xd);
            float ax = fmaxf(fabsf(xd) - MARGIN, 0.f);
            go = __any_sync(0xffffffffu, __fmul_rn(ax, ax) <= d5);
            j++;
        }
    }
#undef CAND
#undef INS

    snb[t*Kv+0] = s0s[i0]; snb[t*Kv+1] = s0s[i1]; snb[t*Kv+2] = s0s[i2];
    snb[t*Kv+3] = s0s[i3]; snb[t*Kv+4] = s0s[i4]; snb[t*Kv+5] = s0s[i5];
    __syncthreads();

    // ---- phase 3: thread t = dim d; FFMA2 over packed (x,y)/(A,B) pairs ----
    const int d = t;
    const float4 wv = sW3[d];
    const ull w01 = f2pack(wv.x, wv.y);
    ull AB[Kv];
#pragma unroll
    for (int k = 0; k < Kv; k++) AB[k] = *(const ull*)&sAB[k * Dv + d];

    float acc = 0.f;
#pragma unroll 4
    for (int r = 0; r < RPB; r++) {
        float4 rd = srow[r];                     // broadcast LDS.128
        const ulonglong2* nbp = (const ulonglong2*)(snb + r * Kv);
        ulonglong2 q0 = nbp[0], q1 = nbp[1], q2 = nbp[2];   // 3x LDS.128
        ull s2 = f2pack(wv.w, __fmul_rn(rd.z, wv.z));       // (base, dl*w2)
        s2 = f2fma(f2pack(rd.x, rd.y), w01, s2);
        s2 = f2fma(q0.x, AB[0], s2);
        s2 = f2fma(q0.y, AB[1], s2);
        s2 = f2fma(q1.x, AB[2], s2);
        s2 = f2fma(q1.y, AB[3], s2);
        s2 = f2fma(q2.x, AB[4], s2);
        s2 = f2fma(q2.y, AB[5], s2);
        float lo, hi; f2unpack(s2, lo, hi);
        float v = __fadd_rn(lo, hi);
        v = fmaxf(v, 0.01f * v);                 // leaky_relu(0.01)
        int orow = __float_as_int(rd.w);
        h_out[((size_t)b * 1025 + 1 + orow) * Dv + d] = v;
        acc += v;
    }
    g_partial[((size_t)b * CHUNKS + chunk) * Dv + d] = acc;

    // ---- fused tail: last finishing block computes depot row + means ----
    __threadfence();
    if (t == 0) sLast = (atomicAdd(&g_count, 1) == CHUNKS * Bv - 1) ? 1 : 0;
    __syncthreads();
    if (sLast) {
        float w0 = Wdep[t * 2 + 0], w1 = Wdep[t * 2 + 1], bd = bdep[t];
        for (int bb = 0; bb < Bv; bb++) {
            float v = bd;
            v = fmaf(depot[bb * 2 + 0], w0, v);
            v = fmaf(depot[bb * 2 + 1], w1, v);
            v = fmaxf(v, 0.01f * v);
            h_out[(size_t)bb * 1025 * Dv + t] = v;       // h[bb, 0, d]
            float s = v;
#pragma unroll
            for (int c = 0; c < CHUNKS; c++)
                s += g_partial[((size_t)bb * CHUNKS + c) * Dv + t];
            h_out[(size_t)Bv * 1025 * Dv + bb * Dv + t] = s / 1025.0f;
        }
        if (t == 0) g_count = 0;                 // reset for next graph replay
    }
}

// ---------------------------------------------------------------------------
extern "C" void kernel_launch(void* const* d_in, const int* in_sizes, int n_in,
                              void* d_out, int out_size)
{
    const float* loc      = (const float*)d_in[0];
    const float* deadline = (const float*)d_in[1];
    const float* depot    = (const float*)d_in[2];
    const float* W3d      = (const float*)d_in[3];
    const float* b3d      = (const float*)d_in[4];
    const float* W2d      = (const float*)d_in[5];
    const float* b2d      = (const float*)d_in[6];
    const float* Wnb      = (const float*)d_in[7];
    const float* bnb      = (const float*)d_in[8];
    const float* Wdep     = (const float*)d_in[9];
    const float* bdep     = (const float*)d_in[10];
    float* out = (float*)d_out;

    setup_kernel<<<Bv + 48, 512>>>(loc, deadline, W2d, b2d, Wnb);
    dim3 grid(CHUNKS, Bv);
    main_kernel<<<grid, THR>>>(W3d, b3d, bnb, depot, Wdep, bdep, out);
}